// round 10
// baseline (speedup 1.0000x reference)
#include <cuda_runtime.h>
#include <cuda_bf16.h>
#include <cstdint>

// Problem constants
#define BB   128
#define SS   37
#define TT   2048
#define DD   256
#define STT  8
#define CC   2
#define MER  264
#define NF   74

#define NT      512
#define DSTAGE  6                    // pipeline depth
#define ROWB    8192                 // bytes per row (2048 f32)
#define STAGE_BYTES (2 * ROWB)       // x row + mask row
#define SMEM_DYN (DSTAGE * STAGE_BYTES)   // 96 KB ring

// per-warp partial layout: 76 quantities x 4 partials
#define PW   312

// tail merge GEMV split
#define G2   6
#define Q2   66
#define KI2  (MER / G2)   // 44

__device__ __forceinline__ float wredf(float v) {
    #pragma unroll
    for (int o = 16; o; o >>= 1) v += __shfl_xor_sync(0xffffffffu, v, o);
    return v;
}
// 3-level: lanes 0-3 hold 4 disjoint partials
__device__ __forceinline__ float wred3(float v) {
    v += __shfl_xor_sync(0xffffffffu, v, 16);
    v += __shfl_xor_sync(0xffffffffu, v, 8);
    v += __shfl_xor_sync(0xffffffffu, v, 4);
    return v;
}
__device__ __forceinline__ void pf_l2(const void* p) {
    asm volatile("prefetch.global.L2 [%0];" :: "l"(p));
}

// ---- mbarrier / bulk-async primitives (1-D, no tensormap) ----
__device__ __forceinline__ void mbar_init(uint32_t addr, uint32_t cnt) {
    asm volatile("mbarrier.init.shared::cta.b64 [%0], %1;" :: "r"(addr), "r"(cnt) : "memory");
}
__device__ __forceinline__ void mbar_expect_tx(uint32_t addr, uint32_t tx) {
    asm volatile("mbarrier.arrive.expect_tx.shared::cta.b64 _, [%0], %1;"
                 :: "r"(addr), "r"(tx) : "memory");
}
__device__ __forceinline__ void bulk_g2s(uint32_t dst, const void* src, uint32_t bytes, uint32_t mbar) {
    asm volatile("cp.async.bulk.shared::cta.global.mbarrier::complete_tx::bytes [%0], [%1], %2, [%3];"
                 :: "r"(dst), "l"(src), "r"(bytes), "r"(mbar) : "memory");
}
__device__ __forceinline__ void mbar_wait(uint32_t addr, uint32_t phase) {
    asm volatile(
        "{\n\t"
        ".reg .pred P1;\n\t"
        "LAB_WAIT_%=:\n\t"
        "mbarrier.try_wait.parity.acquire.cta.shared::cta.b64 P1, [%0], %1;\n\t"
        "@P1 bra.uni LAB_DONE_%=;\n\t"
        "bra.uni LAB_WAIT_%=;\n\t"
        "LAB_DONE_%=:\n\t"
        "}"
        :: "r"(addr), "r"(phase) : "memory");
}

__device__ __forceinline__ void issue_stage(uint32_t dyn0, uint32_t mb0, int slot, int s,
                                            const char* xrow0, const char* mrow0) {
    const uint32_t mb   = mb0 + 8u * slot;
    const uint32_t dstX = dyn0 + (uint32_t)slot * STAGE_BYTES;
    mbar_expect_tx(mb, STAGE_BYTES);
    bulk_g2s(dstX,        xrow0 + (size_t)s * ROWB, ROWB, mb);
    bulk_g2s(dstX + ROWB, mrow0 + (size_t)s * ROWB, ROWB, mb);
}

__global__ __launch_bounds__(NT, 1)
void fused_kernel(const float* __restrict__ x,
                  const int*   __restrict__ smask,
                  const float* __restrict__ tim,
                  const float* __restrict__ stat,
                  const float* __restrict__ Ws,   // [NF, DD]
                  const float* __restrict__ bs,
                  const float* __restrict__ Wt,   // [1, DD]
                  const float* __restrict__ bt,
                  const float* __restrict__ Wst,  // [STT, STT]
                  const float* __restrict__ bst,
                  const float* __restrict__ Wm,   // [MER, MER]
                  const float* __restrict__ bm,
                  const float* __restrict__ Wc,   // [MER, CC]
                  const float* __restrict__ bc,
                  float* __restrict__ out) {
    extern __shared__ float4 dynbuf[];   // [DSTAGE][1024] float4: x(512) | mask(512)

    const int b    = blockIdx.x;
    const int tid  = threadIdx.x;
    const int w    = tid >> 5;
    const int lane = tid & 31;

    __shared__ float  sW[16 * PW];      // per-warp partials [warp][76*4]  ~20 KB
    __shared__ float  sAll[80];
    __shared__ float  comb[MER];
    __shared__ float4 sH4[G2 * Q2];
    __shared__ float  outc[CC];
    __shared__ unsigned long long mbar[DSTAGE];

    const uint32_t mb0  = (uint32_t)__cvta_generic_to_shared(&mbar[0]);
    const uint32_t dyn0 = (uint32_t)__cvta_generic_to_shared(dynbuf);

    if (tid < CC) outc[tid] = 0.f;
    if (tid == 0) {
        #pragma unroll
        for (int s = 0; s < DSTAGE; ++s) mbar_init(mb0 + 8u * s, 1);
    }

    // ---- L2 prefetch of all weights (spread across grid), fire-and-forget ----
    {
        unsigned r = (unsigned)b * NT + tid;
        const unsigned LWs = (NF * DD * 4) / 128;     // 592
        const unsigned LWm = (MER * MER * 4) / 128;   // 2178
        if (r < LWs) { pf_l2((const char*)Ws + r * 128u); }
        else { r -= LWs;
        if (r < LWm) { pf_l2((const char*)Wm + r * 128u); }
        else { r -= LWm;
        if (r < 17) { pf_l2((const char*)Wc + r * 128u); }
        else { r -= 17;
        if (r < 8) { pf_l2((const char*)bs + r * 128u); }
        else { r -= 8;
        if (r < 8) { pf_l2((const char*)bt + r * 128u); }
        else { r -= 8;
        if (r < 8) { pf_l2((const char*)Wt + r * 128u); }
        else { r -= 8;
        if (r < 9) { pf_l2((const char*)bm + r * 128u); }
        else { r -= 9;
        if (r < 32) { pf_l2((const char*)stat + r * 128u); }
        else { r -= 32;
        if (r < 2) { pf_l2((const char*)Wst + r * 128u); }
        else { r -= 2;
        if (r < 1) { pf_l2((const char*)bst); }
        else { r -= 1;
        if (r < 1) { pf_l2((const char*)bc); }
        }}}}}}}}}}
    }
    __syncthreads();   // mbarrier init visible to all before waits/issues

    const char* xrow0 = (const char*)x     + (size_t)b * SS * ROWB;
    const char* mrow0 = (const char*)smask + (size_t)b * SS * ROWB;

    // prologue: fill the pipeline
    if (tid == 0) {
        #pragma unroll
        for (int s = 0; s < DSTAGE; ++s) issue_stage(dyn0, mb0, s, s, xrow0, mrow0);
    }

    // independent: time row
    const float4 tv = ((const float4*)(tim + (size_t)b * TT))[tid];

    // ================= Phase 1: consume SS row-pairs from the ring =================
    float nz0 = 0.f, nz1 = 0.f, nz2 = 0.f, nz3 = 0.f;
    float* myrow = &sW[w * PW];

    int slot = 0, ph = 0;
    for (int s = 0; s < SS; ++s) {
        mbar_wait(mb0 + 8u * slot, (uint32_t)ph);

        const float4* sx = dynbuf + (size_t)slot * 1024;
        const float4  xv = sx[tid];
        const int4    mv = ((const int4*)(sx + 512))[tid];

        float ax = (xv.x + xv.y) + (xv.z + xv.w);
        float am = (float)((mv.x + mv.y) + (mv.z + mv.w));

        nz0 += fabsf(xv.x) + (float)mv.x;
        nz1 += fabsf(xv.y) + (float)mv.y;
        nz2 += fabsf(xv.z) + (float)mv.z;
        nz3 += fabsf(xv.w) + (float)mv.w;

        ax = wred3(ax);
        am = wred3(am);
        if (lane < 4) {
            myrow[s * 4 + lane]        = ax;
            myrow[(SS + s) * 4 + lane] = am;
        }

        __syncthreads();   // all reads of this slot done
        if (tid == 0 && s + DSTAGE < SS)
            issue_stage(dyn0, mb0, slot, s + DSTAGE, xrow0, mrow0);

        if (++slot == DSTAGE) { slot = 0; ph ^= 1; }
    }

    // mask count + masked time sum (each thread saw ALL sensors at its 4 t's)
    {
        float ms = 0.f, tm = 0.f;
        if (nz0 > 0.f) { ms += 1.f; tm += tv.x; }
        if (nz1 > 0.f) { ms += 1.f; tm += tv.y; }
        if (nz2 > 0.f) { ms += 1.f; tm += tv.z; }
        if (nz3 > 0.f) { ms += 1.f; tm += tv.w; }
        ms = wred3(ms);
        tm = wred3(tm);
        if (lane < 4) {
            myrow[74 * 4 + lane] = ms;
            myrow[75 * 4 + lane] = tm;
        }
    }
    __syncthreads();

    // final combine: 76 outputs, 16 warp-rows x 4 partials each
    if (tid < 76) {
        float acc = 0.f;
        #pragma unroll
        for (int w2 = 0; w2 < 16; ++w2) {
            const float4 p = *(const float4*)&sW[w2 * PW + tid * 4];
            acc += (p.x + p.y) + (p.z + p.w);
        }
        sAll[tid] = acc;
    }
    __syncthreads();

    // ================= Phase 2: per-batch tail (L2-warm) =================
    const float msum  = sAll[74];
    const float tmsum = sAll[75];
    const float inv   = 1.f / fmaxf(msum, 1e-9f);

    // ---- A: comb[MER] ----
    if (tid < DD) {
        float acc = 0.f;
        #pragma unroll 8
        for (int f = 0; f < NF; ++f) acc += sAll[f] * Ws[f * DD + tid];
        acc += msum * (bs[tid] + bt[tid]) + tmsum * Wt[tid];
        comb[tid] = acc * inv;
    } else if (tid < MER) {
        const int j = tid - DD;
        float acc = bst[j];
        #pragma unroll
        for (int q = 0; q < STT; ++q) acc += stat[b * STT + q] * Wst[q * STT + j];
        comb[tid] = acc;
    }
    __syncthreads();

    // ---- B: merge GEMV split-i, float4 columns ----
    if (tid < G2 * Q2) {
        const int q  = tid % Q2;
        const int gg = tid / Q2;
        const float4* __restrict__ Wm4 = (const float4*)Wm;
        float4 acc = make_float4(0.f, 0.f, 0.f, 0.f);
        #pragma unroll
        for (int kk = 0; kk < KI2; ++kk) {
            const int ii = gg * KI2 + kk;
            const float  c  = comb[ii];
            const float4 wv = Wm4[ii * Q2 + q];
            acc.x += c * wv.x;
            acc.y += c * wv.y;
            acc.z += c * wv.z;
            acc.w += c * wv.w;
        }
        sH4[gg * Q2 + q] = acc;
    }
    __syncthreads();

    // ---- C: reduce, ReLU, classifier ----
    float p0 = 0.f, p1 = 0.f;
    if (tid < MER) {
        const float* sH = (const float*)sH4;
        float t = bm[tid];
        #pragma unroll
        for (int gg = 0; gg < G2; ++gg) t += sH[gg * MER + tid];
        const float h = fmaxf(t, 0.f);
        p0 = h * Wc[tid * CC + 0];
        p1 = h * Wc[tid * CC + 1];
    }
    p0 = wredf(p0);
    p1 = wredf(p1);
    if (lane == 0) {
        atomicAdd(&outc[0], p0);
        atomicAdd(&outc[1], p1);
    }
    __syncthreads();

    if (tid < CC) out[b * CC + tid] = outc[tid] + bc[tid];
}

// ---------------- launch ----------------
extern "C" void kernel_launch(void* const* d_in, const int* in_sizes, int n_in,
                              void* d_out, int out_size) {
    const float* x     = (const float*)d_in[0];
    const float* stat  = (const float*)d_in[1];
    const float* tim   = (const float*)d_in[2];
    const int*   smask = (const int*)  d_in[3];
    const float* Ws    = (const float*)d_in[4];
    const float* bs    = (const float*)d_in[5];
    const float* Wt    = (const float*)d_in[6];
    const float* bt    = (const float*)d_in[7];
    const float* Wst   = (const float*)d_in[8];
    const float* bst   = (const float*)d_in[9];
    const float* Wm    = (const float*)d_in[10];
    const float* bm    = (const float*)d_in[11];
    const float* Wc    = (const float*)d_in[12];
    const float* bc    = (const float*)d_in[13];
    float* out = (float*)d_out;

    cudaFuncSetAttribute(fused_kernel,
                         cudaFuncAttributeMaxDynamicSharedMemorySize, SMEM_DYN);
    fused_kernel<<<BB, NT, SMEM_DYN>>>(x, smask, tim, stat, Ws, bs, Wt, bt,
                                       Wst, bst, Wm, bm, Wc, bc, out);
}